// round 1
// baseline (speedup 1.0000x reference)
#include <cuda_runtime.h>
#include <cuda_bf16.h>

#define NQ 11
#define NSTATE 2048
#define BATCH 128
#define SEQ 48
#define FEAT 60
#define NH 5
#define NV 6
#define NTHREADS 128
#define TWO_PI 6.2831853071795864769f

__device__ __forceinline__ float2 cmulf(float2 a, float2 b) {
    return make_float2(a.x*b.x - a.y*b.y, a.x*b.y + a.y*b.x);
}

__device__ __forceinline__ void apply_gate(float* sre, float* sim,
                                           const float2* m, int bp, int tid) {
    const float2 m00 = m[0], m01 = m[1], m10 = m[2], m11 = m[3];
    const int mask = (1 << bp) - 1;
    #pragma unroll
    for (int it = 0; it < 8; ++it) {
        int p  = tid + it * NTHREADS;          // 1024 pairs total
        int i0 = ((p & ~mask) << 1) | (p & mask);
        int i1 = i0 | (1 << bp);
        float a0r = sre[i0], a0i = sim[i0];
        float a1r = sre[i1], a1i = sim[i1];
        sre[i0] = m00.x*a0r - m00.y*a0i + m01.x*a1r - m01.y*a1i;
        sim[i0] = m00.x*a0i + m00.y*a0r + m01.x*a1i + m01.y*a1r;
        sre[i1] = m10.x*a0r - m10.y*a0i + m11.x*a1r - m11.y*a1i;
        sim[i1] = m10.x*a0i + m10.y*a0r + m11.x*a1i + m11.y*a1r;
    }
    __syncthreads();
}

__device__ __forceinline__ void apply_crx(float* sre, float* sim,
                                          float c, float s, int bc, int tid) {
    const int bt = bc - 1;
    const int maskt = (1 << bt) - 1;
    #pragma unroll
    for (int it = 0; it < 4; ++it) {
        int p  = tid + it * NTHREADS;          // 512 pairs (control bit = 1)
        int i0 = ((p & ~maskt) << 2) | (1 << bc) | (p & maskt);
        int i1 = i0 | (1 << bt);
        float a0r = sre[i0], a0i = sim[i0];
        float a1r = sre[i1], a1i = sim[i1];
        // a0' = c*a0 - i*s*a1 ; a1' = -i*s*a0 + c*a1
        sre[i0] = c*a0r + s*a1i;
        sim[i0] = c*a0i - s*a1r;
        sre[i1] = s*a0i + c*a1r;
        sim[i1] = c*a1i - s*a0r;
    }
    __syncthreads();
}

__global__ __launch_bounds__(NTHREADS)
void qrnn_kernel(const float* __restrict__ x,
                 const float* __restrict__ hidden,
                 const float* __restrict__ params,
                 float* __restrict__ out) {
    const int b   = blockIdx.x;
    const int tid = threadIdx.x;

    __shared__ float sre[NSTATE];
    __shared__ float sim[NSTATE];
    __shared__ float2 U[22][4];      // fused RZ*RY*RX per (layer, qubit)
    __shared__ float2 crx[8];        // (cos, sin) per (layer, pair)
    __shared__ float2 cs[NQ];        // (cos(a/2), sin(a/2)) per qubit
    __shared__ float pooled[NV];
    __shared__ float hbuf[NH];
    __shared__ float red[4][NQ];

    // ---- precompute fused gates (params fixed over time & batch) ----
    if (tid < 22) {
        int l = tid / 11, q = tid % 11;
        int p0 = l * 37 + (q < 5 ? 3 * q : 19 + 3 * (q - 5));
        float t1 = params[p0] * 0.5f, t2 = params[p0+1] * 0.5f, t3 = params[p0+2] * 0.5f;
        float c1 = cosf(t1), s1 = sinf(t1);
        float c2 = cosf(t2), s2 = sinf(t2);
        float c3 = cosf(t3), s3 = sinf(t3);
        // RX = [[c1, -i s1], [-i s1, c1]]
        float2 a00 = make_float2(c1, 0.f), a01 = make_float2(0.f, -s1);
        float2 a10 = a01, a11 = a00;
        // RY*RX, RY = [[c2, -s2],[s2, c2]]
        float2 m00 = make_float2(c2*a00.x - s2*a10.x, c2*a00.y - s2*a10.y);
        float2 m01 = make_float2(c2*a01.x - s2*a11.x, c2*a01.y - s2*a11.y);
        float2 m10 = make_float2(s2*a00.x + c2*a10.x, s2*a00.y + c2*a10.y);
        float2 m11 = make_float2(s2*a01.x + c2*a11.x, s2*a01.y + c2*a11.y);
        // RZ: row0 *= (c3 - i s3), row1 *= (c3 + i s3)
        float2 r0 = make_float2(c3, -s3), r1 = make_float2(c3, s3);
        U[tid][0] = cmulf(r0, m00); U[tid][1] = cmulf(r0, m01);
        U[tid][2] = cmulf(r1, m10); U[tid][3] = cmulf(r1, m11);
    }
    if (tid < 8) {
        int l = tid / 4, k = tid % 4;
        float th = params[l * 37 + 15 + k] * 0.5f;
        crx[tid] = make_float2(cosf(th), sinf(th));
    }
    if (tid < NH) hbuf[tid] = hidden[b * NH + tid];
    __syncthreads();

    for (int t = 0; t < SEQ; ++t) {
        // ---- preprocess: window means, min/max scale to [0, 2pi] ----
        if (tid < NV) {
            const float* xp = x + (b * SEQ + t) * FEAT + tid * 10;
            float s = 0.f;
            #pragma unroll
            for (int j = 0; j < 10; ++j) s += xp[j];
            pooled[tid] = s * 0.1f;
        }
        __syncthreads();
        if (tid == 0) {
            float mn = pooled[0], mx = pooled[0];
            #pragma unroll
            for (int v = 1; v < NV; ++v) {
                mn = fminf(mn, pooled[v]);
                mx = fmaxf(mx, pooled[v]);
            }
            float scale = TWO_PI / (mx - mn + 1e-8f);
            #pragma unroll
            for (int q = 0; q < NH; ++q) {
                float a = hbuf[q] * 0.5f;
                cs[q] = make_float2(cosf(a), sinf(a));
            }
            #pragma unroll
            for (int v = 0; v < NV; ++v) {
                float a = scale * (pooled[v] - mn) * 0.5f;
                cs[NH + v] = make_float2(cosf(a), sinf(a));
            }
        }
        __syncthreads();

        // ---- embed product state: amp(i) = prod(c/s) * (-i)^popcount ----
        {
            // idx = tid*16 + j; idx bits 4..10 = tid bits 0..6 (qubits 6..0)
            float phi = 1.f; int khi = 0;
            #pragma unroll
            for (int bpos = 4; bpos <= 10; ++bpos) {
                int q = 10 - bpos;
                if ((tid >> (bpos - 4)) & 1) { phi *= cs[q].y; khi++; }
                else                          phi *= cs[q].x;
            }
            #pragma unroll
            for (int j = 0; j < 16; ++j) {
                float pr = phi; int k = khi;
                #pragma unroll
                for (int bpos = 0; bpos < 4; ++bpos) {
                    int q = 10 - bpos;
                    if ((j >> bpos) & 1) { pr *= cs[q].y; k++; }
                    else                  pr *= cs[q].x;
                }
                int idx = tid * 16 + j;
                float re, im;
                switch (k & 3) {
                    case 0:  re =  pr; im =  0.f; break;
                    case 1:  re =  0.f; im = -pr; break;
                    case 2:  re = -pr; im =  0.f; break;
                    default: re =  0.f; im =  pr; break;
                }
                sre[idx] = re; sim[idx] = im;
            }
        }
        __syncthreads();

        // ---- circuit: 2 layers ----
        #pragma unroll
        for (int l = 0; l < 2; ++l) {
            #pragma unroll
            for (int q = 0; q < 5; ++q)          // hidden qubits, bitpos 10-q
                apply_gate(sre, sim, U[l * 11 + q], 10 - q, tid);
            #pragma unroll
            for (int k = 0; k < 4; ++k)          // CRX(control=k, target=k+1)
                apply_crx(sre, sim, crx[l * 4 + k].x, crx[l * 4 + k].y, 10 - k, tid);
            #pragma unroll
            for (int i = 0; i < 6; ++i)          // visible qubits 5..10, bitpos 5-i
                apply_gate(sre, sim, U[l * 11 + 5 + i], 5 - i, tid);
        }

        // ---- expectations <Z_q> ----
        float tot = 0.f, sb0 = 0.f, sb1 = 0.f, sb2 = 0.f, sb3 = 0.f;
        const int base = tid * 16;
        #pragma unroll
        for (int j = 0; j < 16; ++j) {
            float r = sre[base + j], i = sim[base + j];
            float pr = r * r + i * i;
            tot += pr;
            if (j & 1) sb0 += pr;
            if (j & 2) sb1 += pr;
            if (j & 4) sb2 += pr;
            if (j & 8) sb3 += pr;
        }
        float zl[NQ];
        #pragma unroll
        for (int q = 0; q < 7; ++q) {            // bitpos 10..4 -> tid bits
            int bit = (tid >> (10 - q - 4)) & 1;
            zl[q] = bit ? -tot : tot;
        }
        zl[7]  = tot - 2.f * sb3;
        zl[8]  = tot - 2.f * sb2;
        zl[9]  = tot - 2.f * sb1;
        zl[10] = tot - 2.f * sb0;

        #pragma unroll
        for (int q = 0; q < NQ; ++q) {
            float v = zl[q];
            #pragma unroll
            for (int o = 16; o; o >>= 1)
                v += __shfl_xor_sync(0xffffffff, v, o);
            zl[q] = v;
        }
        const int warp = tid >> 5, lane = tid & 31;
        if (lane == 0) {
            #pragma unroll
            for (int q = 0; q < NQ; ++q) red[warp][q] = zl[q];
        }
        __syncthreads();
        if (tid < NQ) {
            float z = red[0][tid] + red[1][tid] + red[2][tid] + red[3][tid];
            if (tid < NH) hbuf[tid] = z;
            else out[(b * SEQ + t) * NV + (tid - NH)] = z;
        }
        __syncthreads();
    }

    // ---- hidden_final after outputs ----
    if (tid < NH) out[BATCH * SEQ * NV + b * NH + tid] = hbuf[tid];
}

extern "C" void kernel_launch(void* const* d_in, const int* in_sizes, int n_in,
                              void* d_out, int out_size) {
    const float* x      = (const float*)d_in[0];
    const float* hidden = (const float*)d_in[1];
    const float* params = (const float*)d_in[2];
    float* out = (float*)d_out;
    qrnn_kernel<<<BATCH, NTHREADS>>>(x, hidden, params, out);
}

// round 2
// speedup vs baseline: 15.5878x; 15.5878x over previous
#include <cuda_runtime.h>
#include <math.h>

#define NQ 11
#define BATCH 128
#define SEQ 48
#define FEAT 60
#define NH 5
#define NV 6
#define TWO_PI 6.2831853071795864769f

struct C2 { float re, im; };
struct M2 { C2 m00, m01, m10, m11; };

__device__ __forceinline__ C2 cmul(C2 a, C2 b) {
    C2 r; r.re = a.re*b.re - a.im*b.im; r.im = a.re*b.im + a.im*b.re; return r;
}
__device__ __forceinline__ C2 cadd(C2 a, C2 b) { C2 r{a.re+b.re, a.im+b.im}; return r; }

// U = RZ(t3) * RY(t2) * RX(t1)
__device__ __forceinline__ M2 fuse_zyx(float t1, float t2, float t3) {
    float c1,s1,c2,s2,c3,s3;
    sincosf(0.5f*t1, &s1, &c1);
    sincosf(0.5f*t2, &s2, &c2);
    sincosf(0.5f*t3, &s3, &c3);
    // RX
    C2 a00{c1,0.f}, a01{0.f,-s1}, a10{0.f,-s1}, a11{c1,0.f};
    // RY * RX
    C2 m00{c2*a00.re - s2*a10.re, c2*a00.im - s2*a10.im};
    C2 m01{c2*a01.re - s2*a11.re, c2*a01.im - s2*a11.im};
    C2 m10{s2*a00.re + c2*a10.re, s2*a00.im + c2*a10.im};
    C2 m11{s2*a01.re + c2*a11.re, s2*a01.im + c2*a11.im};
    // RZ row phases
    C2 r0{c3,-s3}, r1{c3,s3};
    M2 u;
    u.m00 = cmul(r0,m00); u.m01 = cmul(r0,m01);
    u.m10 = cmul(r1,m10); u.m11 = cmul(r1,m11);
    return u;
}
__device__ __forceinline__ M2 mmul(M2 p, M2 q) {  // p * q
    M2 r;
    r.m00 = cadd(cmul(p.m00,q.m00), cmul(p.m01,q.m10));
    r.m01 = cadd(cmul(p.m00,q.m01), cmul(p.m01,q.m11));
    r.m10 = cadd(cmul(p.m10,q.m00), cmul(p.m11,q.m10));
    r.m11 = cadd(cmul(p.m10,q.m01), cmul(p.m11,q.m11));
    return r;
}

__global__ __launch_bounds__(128)
void qrnn_kernel(const float* __restrict__ x,
                 const float* __restrict__ hidden,
                 const float* __restrict__ params,
                 float* __restrict__ out)
{
    if (blockIdx.x < BATCH) {
        // ============ hidden recurrence: 5-qubit sim, one warp per batch ============
        if (threadIdx.x >= 32) return;
        const int lane = threadIdx.x;
        const int b = blockIdx.x;

        // lane-private layer-0 hidden gate (lane q holds qubit q's matrix)
        M2 h1;
        {
            int q = (lane < 5) ? lane : 0;
            h1 = fuse_zyx(params[3*q], params[3*q+1], params[3*q+2]);
        }
        // uniform: layer-1 hidden gates + both CRX layers (every lane holds all)
        M2 h2[5];
        #pragma unroll
        for (int q = 0; q < 5; q++)
            h2[q] = fuse_zyx(params[37+3*q], params[37+3*q+1], params[37+3*q+2]);
        float crxc[8], crxs[8];
        #pragma unroll
        for (int k = 0; k < 8; k++) {
            int l = k >> 2, kk = k & 3;
            sincosf(0.5f*params[l*37 + 15 + kk], &crxs[k], &crxc[k]);
        }

        float z = (lane < 5) ? hidden[b*NH + lane] : 0.f;

        for (int t = 0; t < SEQ; t++) {
            // angle -> per-qubit 2-vector w = h1 * (cos, -i sin)   (lanes 0..4)
            float cc, ss;
            sincosf(0.5f*z, &ss, &cc);
            float w0r = h1.m00.re*cc + h1.m01.im*ss;
            float w0i = h1.m00.im*cc - h1.m01.re*ss;
            float w1r = h1.m10.re*cc + h1.m11.im*ss;
            float w1i = h1.m10.im*cc - h1.m11.re*ss;

            // build product state: lane holds amp of 5-bit index = lane
            float ar = 1.f, ai = 0.f;
            #pragma unroll
            for (int q = 0; q < 5; q++) {
                float a0r = __shfl_sync(0xffffffffu, w0r, q);
                float a0i = __shfl_sync(0xffffffffu, w0i, q);
                float b1r = __shfl_sync(0xffffffffu, w1r, q);
                float b1i = __shfl_sync(0xffffffffu, w1i, q);
                int bit = (lane >> (4-q)) & 1;
                float vr = bit ? b1r : a0r;
                float vi = bit ? b1i : a0i;
                float nr = ar*vr - ai*vi;
                float ni = ar*vi + ai*vr;
                ar = nr; ai = ni;
            }

            // CRX chain, layer 0: control qubit k (bit 4-k), target k+1 (bit 3-k)
            #pragma unroll
            for (int k = 0; k < 4; k++) {
                int mt = 1 << (3-k);
                float orr = __shfl_xor_sync(0xffffffffu, ar, mt);
                float oii = __shfl_xor_sync(0xffffffffu, ai, mt);
                if (lane & (1 << (4-k))) {
                    float nr = crxc[k]*ar + crxs[k]*oii;
                    float ni = crxc[k]*ai - crxs[k]*orr;
                    ar = nr; ai = ni;
                }
            }

            // layer-1 hidden 1q gates
            #pragma unroll
            for (int q = 0; q < 5; q++) {
                int m = 1 << (4-q);
                float orr = __shfl_xor_sync(0xffffffffu, ar, m);
                float oii = __shfl_xor_sync(0xffffffffu, ai, m);
                int bit = lane & m;
                float car = bit ? h2[q].m11.re : h2[q].m00.re;
                float cai = bit ? h2[q].m11.im : h2[q].m00.im;
                float cbr = bit ? h2[q].m10.re : h2[q].m01.re;
                float cbi = bit ? h2[q].m10.im : h2[q].m01.im;
                float nr = car*ar - cai*ai + cbr*orr - cbi*oii;
                float ni = car*ai + cai*ar + cbr*oii + cbi*orr;
                ar = nr; ai = ni;
            }

            // CRX chain, layer 1
            #pragma unroll
            for (int k = 0; k < 4; k++) {
                int mt = 1 << (3-k);
                float orr = __shfl_xor_sync(0xffffffffu, ar, mt);
                float oii = __shfl_xor_sync(0xffffffffu, ai, mt);
                if (lane & (1 << (4-k))) {
                    float nr = crxc[4+k]*ar + crxs[4+k]*oii;
                    float ni = crxc[4+k]*ai - crxs[4+k]*orr;
                    ar = nr; ai = ni;
                }
            }

            // measure <Z_q>: signed butterfly reductions; lane q keeps z_q
            float p = ar*ar + ai*ai;
            float znext = z;
            #pragma unroll
            for (int q = 0; q < 5; q++) {
                int m = 1 << (4-q);
                float v = (lane & m) ? -p : p;
                #pragma unroll
                for (int o = 16; o >= 1; o >>= 1)
                    v += __shfl_xor_sync(0xffffffffu, v, o);
                if (lane == q) znext = v;
            }
            z = znext;
        }
        if (lane < 5) out[BATCH*SEQ*NV + b*NH + lane] = z;

    } else {
        // ============ outputs: closed form per (b,t), independent of recurrence ============
        __shared__ float Cc[6], Dd[6], Ee[6];
        const int tid = threadIdx.x;
        if (tid < 6) {
            M2 u0 = fuse_zyx(params[19+3*tid],    params[20+3*tid],    params[21+3*tid]);
            M2 u1 = fuse_zyx(params[37+19+3*tid], params[37+20+3*tid], params[37+21+3*tid]);
            M2 M = mmul(u1, u0);
            float h00 = (M.m00.re*M.m00.re + M.m00.im*M.m00.im)
                      - (M.m10.re*M.m10.re + M.m10.im*M.m10.im);
            float h11 = (M.m01.re*M.m01.re + M.m01.im*M.m01.im)
                      - (M.m11.re*M.m11.re + M.m11.im*M.m11.im);
            float imh01 = (M.m00.re*M.m01.im - M.m00.im*M.m01.re)
                        - (M.m10.re*M.m11.im - M.m10.im*M.m11.re);
            Cc[tid] = 0.5f*(h00 + h11);
            Dd[tid] = 0.5f*(h00 - h11);
            Ee[tid] = imh01;
        }
        __syncthreads();

        const int P = (blockIdx.x - BATCH)*128 + tid;   // 0..6143 = b*SEQ + t
        const float4* x4 = (const float4*)(x + (size_t)P * FEAT);
        float vals[60];
        #pragma unroll
        for (int i = 0; i < 15; i++) {
            float4 v = x4[i];
            vals[4*i+0] = v.x; vals[4*i+1] = v.y;
            vals[4*i+2] = v.z; vals[4*i+3] = v.w;
        }
        float pooled[6];
        #pragma unroll
        for (int v = 0; v < 6; v++) {
            float s = 0.f;
            #pragma unroll
            for (int j = 0; j < 10; j++) s += vals[v*10 + j];
            pooled[v] = 0.1f * s;
        }
        float mn = pooled[0], mx = pooled[0];
        #pragma unroll
        for (int v = 1; v < 6; v++) {
            mn = fminf(mn, pooled[v]);
            mx = fmaxf(mx, pooled[v]);
        }
        float scale = TWO_PI / (mx - mn + 1e-8f);
        #pragma unroll
        for (int v = 0; v < 6; v++) {
            float a = scale * (pooled[v] - mn);
            float sa, ca;
            sincosf(a, &sa, &ca);
            out[(size_t)P*6 + v] = Cc[v] + Dd[v]*ca + Ee[v]*sa;
        }
    }
}

extern "C" void kernel_launch(void* const* d_in, const int* in_sizes, int n_in,
                              void* d_out, int out_size) {
    const float* x      = (const float*)d_in[0];
    const float* hidden = (const float*)d_in[1];
    const float* params = (const float*)d_in[2];
    float* out = (float*)d_out;
    qrnn_kernel<<<BATCH + (BATCH*SEQ + 127)/128, 128>>>(x, hidden, params, out);
}

// round 3
// speedup vs baseline: 18.4680x; 1.1848x over previous
#include <cuda_runtime.h>
#include <math.h>

#define BATCH 128
#define SEQ 48
#define FEAT 60
#define NH 5
#define NV 6
#define TWO_PI 6.2831853071795864769f

struct C2 { float re, im; };
struct M2 { C2 m00, m01, m10, m11; };

__device__ __forceinline__ C2 cmul(C2 a, C2 b) {
    C2 r; r.re = a.re*b.re - a.im*b.im; r.im = a.re*b.im + a.im*b.re; return r;
}
__device__ __forceinline__ C2 cadd(C2 a, C2 b) { C2 r{a.re+b.re, a.im+b.im}; return r; }

// U = RZ(t3) * RY(t2) * RX(t1)
__device__ __forceinline__ M2 fuse_zyx(float t1, float t2, float t3) {
    float c1,s1,c2,s2,c3,s3;
    sincosf(0.5f*t1, &s1, &c1);
    sincosf(0.5f*t2, &s2, &c2);
    sincosf(0.5f*t3, &s3, &c3);
    C2 a00{c1,0.f}, a01{0.f,-s1}, a10{0.f,-s1}, a11{c1,0.f};
    C2 m00{c2*a00.re - s2*a10.re, c2*a00.im - s2*a10.im};
    C2 m01{c2*a01.re - s2*a11.re, c2*a01.im - s2*a11.im};
    C2 m10{s2*a00.re + c2*a10.re, s2*a00.im + c2*a10.im};
    C2 m11{s2*a01.re + c2*a11.re, s2*a01.im + c2*a11.im};
    C2 r0{c3,-s3}, r1{c3,s3};
    M2 u;
    u.m00 = cmul(r0,m00); u.m01 = cmul(r0,m01);
    u.m10 = cmul(r1,m10); u.m11 = cmul(r1,m11);
    return u;
}
__device__ __forceinline__ M2 mmul(M2 p, M2 q) {  // p * q
    M2 r;
    r.m00 = cadd(cmul(p.m00,q.m00), cmul(p.m01,q.m10));
    r.m01 = cadd(cmul(p.m00,q.m01), cmul(p.m01,q.m11));
    r.m10 = cadd(cmul(p.m10,q.m00), cmul(p.m11,q.m10));
    r.m11 = cadd(cmul(p.m10,q.m01), cmul(p.m11,q.m11));
    return r;
}

// 1-qubit gate applied to a register-resident 32-vector (static mask)
template<int M>
__device__ __forceinline__ void g1q(float* Sr, float* Si, M2 g) {
    #pragma unroll
    for (int i = 0; i < 32; ++i) {
        if ((i & M) == 0) {
            const int j = i | M;
            float ar = Sr[i], ai = Si[i], br = Sr[j], bi = Si[j];
            Sr[i] = g.m00.re*ar - g.m00.im*ai + g.m01.re*br - g.m01.im*bi;
            Si[i] = g.m00.re*ai + g.m00.im*ar + g.m01.re*bi + g.m01.im*br;
            Sr[j] = g.m10.re*ar - g.m10.im*ai + g.m11.re*br - g.m11.im*bi;
            Si[j] = g.m10.re*ai + g.m10.im*ar + g.m11.re*bi + g.m11.im*br;
        }
    }
}
// CRX(control mask MC, target mask MT) on register-resident 32-vector
template<int MC, int MT>
__device__ __forceinline__ void gcrx(float* Sr, float* Si, float c, float s) {
    #pragma unroll
    for (int i = 0; i < 32; ++i) {
        if ((i & MC) != 0 && (i & MT) == 0) {
            const int j = i | MT;
            float a0r = Sr[i], a0i = Si[i], a1r = Sr[j], a1i = Si[j];
            Sr[i] = c*a0r + s*a1i;
            Si[i] = c*a0i - s*a1r;
            Sr[j] = s*a0i + c*a1r;
            Si[j] = c*a1i - s*a0r;
        }
    }
}

__global__ __launch_bounds__(128)
void qrnn_kernel(const float* __restrict__ x,
                 const float* __restrict__ hidden,
                 const float* __restrict__ params,
                 float* __restrict__ out)
{
    const int b = blockIdx.x;
    __shared__ float Tre[32][33];
    __shared__ float Tim[32][33];

    if (threadIdx.x < 32) {
        // ================= warp 0: hidden recurrence (5-qubit sim) =================
        const int lane = threadIdx.x;

        // layer-0 hidden gate for this lane's qubit (lanes 0..4)
        M2 h1;
        {
            int q = (lane < 5) ? lane : 0;
            h1 = fuse_zyx(params[3*q], params[3*q+1], params[3*q+2]);
        }

        // ---- precompute the fixed 32x32 unitary U = CRX1 * G2 * CRX0 ----
        // lane j builds COLUMN j entirely in registers (no shuffles)
        float Rr[32], Ri[32];
        {
            M2 h2[5];
            #pragma unroll
            for (int q = 0; q < 5; q++)
                h2[q] = fuse_zyx(params[37+3*q], params[37+3*q+1], params[37+3*q+2]);
            float cx[8], sx[8];
            #pragma unroll
            for (int k = 0; k < 8; k++) {
                int l = k >> 2, kk = k & 3;
                sincosf(0.5f*params[l*37 + 15 + kk], &sx[k], &cx[k]);
            }

            float Sr[32], Si[32];
            #pragma unroll
            for (int i = 0; i < 32; ++i) { Sr[i] = (i == lane) ? 1.f : 0.f; Si[i] = 0.f; }

            // layer-0 CRX chain: control k (mask 1<<(4-k)), target k+1 (mask 1<<(3-k))
            gcrx<16,8>(Sr, Si, cx[0], sx[0]);
            gcrx< 8,4>(Sr, Si, cx[1], sx[1]);
            gcrx< 4,2>(Sr, Si, cx[2], sx[2]);
            gcrx< 2,1>(Sr, Si, cx[3], sx[3]);
            // layer-1 1q gates on hidden qubits
            g1q<16>(Sr, Si, h2[0]);
            g1q< 8>(Sr, Si, h2[1]);
            g1q< 4>(Sr, Si, h2[2]);
            g1q< 2>(Sr, Si, h2[3]);
            g1q< 1>(Sr, Si, h2[4]);
            // layer-1 CRX chain
            gcrx<16,8>(Sr, Si, cx[4], sx[4]);
            gcrx< 8,4>(Sr, Si, cx[5], sx[5]);
            gcrx< 4,2>(Sr, Si, cx[6], sx[6]);
            gcrx< 2,1>(Sr, Si, cx[7], sx[7]);

            // transpose via padded SMEM: lane i ends with ROW i
            #pragma unroll
            for (int i = 0; i < 32; ++i) { Tre[i][lane] = Sr[i]; Tim[i][lane] = Si[i]; }
            __syncwarp();
            #pragma unroll
            for (int j = 0; j < 32; ++j) { Rr[j] = Tre[lane][j]; Ri[j] = Tim[lane][j]; }
        }

        float z = (lane < 5) ? hidden[b*NH + lane] : 0.f;

        #pragma unroll 1
        for (int t = 0; t < SEQ; ++t) {
            // ---- per-qubit 2-vector w = h1 * (cos, -i sin) (lanes 0..4) ----
            float cc, ss;
            sincosf(0.5f*z, &ss, &cc);
            float w0r = h1.m00.re*cc + h1.m01.im*ss;
            float w0i = h1.m00.im*cc - h1.m01.re*ss;
            float w1r = h1.m10.re*cc + h1.m11.im*ss;
            float w1i = h1.m10.im*cc - h1.m11.re*ss;

            // ---- embed: broadcast w, then depth-3 complex product tree ----
            float vr[5], vi[5];
            #pragma unroll
            for (int q = 0; q < 5; q++) {
                float a0r = __shfl_sync(0xffffffffu, w0r, q);
                float a0i = __shfl_sync(0xffffffffu, w0i, q);
                float b1r = __shfl_sync(0xffffffffu, w1r, q);
                float b1i = __shfl_sync(0xffffffffu, w1i, q);
                int bit = (lane >> (4 - q)) & 1;
                vr[q] = bit ? b1r : a0r;
                vi[q] = bit ? b1i : a0i;
            }
            float p01r = vr[0]*vr[1] - vi[0]*vi[1], p01i = vr[0]*vi[1] + vi[0]*vr[1];
            float p23r = vr[2]*vr[3] - vi[2]*vi[3], p23i = vr[2]*vi[3] + vi[2]*vr[3];
            float p03r = p01r*p23r - p01i*p23i,     p03i = p01r*p23i + p01i*p23r;
            float ar   = p03r*vr[4] - p03i*vi[4],   ai   = p03r*vi[4] + p03i*vr[4];

            // ---- dense matvec: amp' = U * amp (broadcast amps, 4 accumulators) ----
            float aR0=0.f,aR1=0.f,aR2=0.f,aR3=0.f;
            float aI0=0.f,aI1=0.f,aI2=0.f,aI3=0.f;
            #pragma unroll
            for (int j = 0; j < 32; j += 4) {
                float b0r = __shfl_sync(0xffffffffu, ar, j+0);
                float b0i = __shfl_sync(0xffffffffu, ai, j+0);
                float b1r = __shfl_sync(0xffffffffu, ar, j+1);
                float b1i = __shfl_sync(0xffffffffu, ai, j+1);
                float b2r = __shfl_sync(0xffffffffu, ar, j+2);
                float b2i = __shfl_sync(0xffffffffu, ai, j+2);
                float b3r = __shfl_sync(0xffffffffu, ar, j+3);
                float b3i = __shfl_sync(0xffffffffu, ai, j+3);
                aR0 = fmaf(Rr[j+0], b0r, fmaf(-Ri[j+0], b0i, aR0));
                aI0 = fmaf(Rr[j+0], b0i, fmaf( Ri[j+0], b0r, aI0));
                aR1 = fmaf(Rr[j+1], b1r, fmaf(-Ri[j+1], b1i, aR1));
                aI1 = fmaf(Rr[j+1], b1i, fmaf( Ri[j+1], b1r, aI1));
                aR2 = fmaf(Rr[j+2], b2r, fmaf(-Ri[j+2], b2i, aR2));
                aI2 = fmaf(Rr[j+2], b2i, fmaf( Ri[j+2], b2r, aI2));
                aR3 = fmaf(Rr[j+3], b3r, fmaf(-Ri[j+3], b3i, aR3));
                aI3 = fmaf(Rr[j+3], b3i, fmaf( Ri[j+3], b3r, aI3));
            }
            float nar = (aR0 + aR1) + (aR2 + aR3);
            float nai = (aI0 + aI1) + (aI2 + aI3);

            // ---- measure all <Z_q> with one Walsh-Hadamard butterfly ----
            float p = nar*nar + nai*nai;
            float v = p;
            #pragma unroll
            for (int m = 16; m >= 1; m >>= 1) {
                float o = __shfl_xor_sync(0xffffffffu, v, m);
                v = (lane & m) ? (o - v) : (v + o);
            }
            // lane (1 << (4-q)) holds z_q; route to lane q
            int src = (lane < 5) ? (1 << (4 - lane)) : 0;
            float znew = __shfl_sync(0xffffffffu, v, src);
            z = (lane < 5) ? znew : 0.f;
        }
        if (lane < 5) out[BATCH*SEQ*NV + b*NH + lane] = z;

    } else {
        // ============ warps 1-3: closed-form outputs for this batch ============
        const int t = threadIdx.x - 32;
        if (t >= SEQ) return;

        // per-thread visible-qubit constants (params fixed)
        float Cc[6], Dd[6], Ee[6];
        #pragma unroll
        for (int q = 0; q < 6; q++) {
            M2 u0 = fuse_zyx(params[19+3*q],    params[20+3*q],    params[21+3*q]);
            M2 u1 = fuse_zyx(params[37+19+3*q], params[37+20+3*q], params[37+21+3*q]);
            M2 M = mmul(u1, u0);
            float h00 = (M.m00.re*M.m00.re + M.m00.im*M.m00.im)
                      - (M.m10.re*M.m10.re + M.m10.im*M.m10.im);
            float h11 = (M.m01.re*M.m01.re + M.m01.im*M.m01.im)
                      - (M.m11.re*M.m11.re + M.m11.im*M.m11.im);
            float imh01 = (M.m00.re*M.m01.im - M.m00.im*M.m01.re)
                        - (M.m10.re*M.m11.im - M.m10.im*M.m11.re);
            Cc[q] = 0.5f*(h00 + h11);
            Dd[q] = 0.5f*(h00 - h11);
            Ee[q] = imh01;
        }

        const int P = b * SEQ + t;
        const float4* x4 = (const float4*)(x + (size_t)P * FEAT);
        float vals[60];
        #pragma unroll
        for (int i = 0; i < 15; i++) {
            float4 v4 = x4[i];
            vals[4*i+0] = v4.x; vals[4*i+1] = v4.y;
            vals[4*i+2] = v4.z; vals[4*i+3] = v4.w;
        }
        float pooled[6];
        #pragma unroll
        for (int v = 0; v < 6; v++) {
            float s = 0.f;
            #pragma unroll
            for (int j = 0; j < 10; j++) s += vals[v*10 + j];
            pooled[v] = 0.1f * s;
        }
        float mn = pooled[0], mx = pooled[0];
        #pragma unroll
        for (int v = 1; v < 6; v++) {
            mn = fminf(mn, pooled[v]);
            mx = fmaxf(mx, pooled[v]);
        }
        float scale = TWO_PI / (mx - mn + 1e-8f);
        #pragma unroll
        for (int v = 0; v < 6; v++) {
            float a = scale * (pooled[v] - mn);
            float sa, ca;
            sincosf(a, &sa, &ca);
            out[(size_t)P*6 + v] = Cc[v] + Dd[v]*ca + Ee[v]*sa;
        }
    }
}

extern "C" void kernel_launch(void* const* d_in, const int* in_sizes, int n_in,
                              void* d_out, int out_size) {
    const float* x      = (const float*)d_in[0];
    const float* hidden = (const float*)d_in[1];
    const float* params = (const float*)d_in[2];
    float* out = (float*)d_out;
    qrnn_kernel<<<BATCH, 128>>>(x, hidden, params, out);
}

// round 4
// speedup vs baseline: 19.9682x; 1.0812x over previous
#include <cuda_runtime.h>
#include <math.h>

#define BATCH 128
#define SEQ 48
#define FEAT 60
#define NH 5
#define NV 6
#define TWO_PI 6.2831853071795864769f

struct C2 { float re, im; };
struct M2 { C2 m00, m01, m10, m11; };

__device__ __forceinline__ C2 cmul(C2 a, C2 b) {
    C2 r; r.re = a.re*b.re - a.im*b.im; r.im = a.re*b.im + a.im*b.re; return r;
}
__device__ __forceinline__ C2 cadd(C2 a, C2 b) { C2 r{a.re+b.re, a.im+b.im}; return r; }

// U = RZ(t3) * RY(t2) * RX(t1)  (precise sincosf: runs once)
__device__ __forceinline__ M2 fuse_zyx(float t1, float t2, float t3) {
    float c1,s1,c2,s2,c3,s3;
    sincosf(0.5f*t1, &s1, &c1);
    sincosf(0.5f*t2, &s2, &c2);
    sincosf(0.5f*t3, &s3, &c3);
    C2 a00{c1,0.f}, a01{0.f,-s1}, a10{0.f,-s1}, a11{c1,0.f};
    C2 m00{c2*a00.re - s2*a10.re, c2*a00.im - s2*a10.im};
    C2 m01{c2*a01.re - s2*a11.re, c2*a01.im - s2*a11.im};
    C2 m10{s2*a00.re + c2*a10.re, s2*a00.im + c2*a10.im};
    C2 m11{s2*a01.re + c2*a11.re, s2*a01.im + c2*a11.im};
    C2 r0{c3,-s3}, r1{c3,s3};
    M2 u;
    u.m00 = cmul(r0,m00); u.m01 = cmul(r0,m01);
    u.m10 = cmul(r1,m10); u.m11 = cmul(r1,m11);
    return u;
}
__device__ __forceinline__ M2 mmul(M2 p, M2 q) {
    M2 r;
    r.m00 = cadd(cmul(p.m00,q.m00), cmul(p.m01,q.m10));
    r.m01 = cadd(cmul(p.m00,q.m01), cmul(p.m01,q.m11));
    r.m10 = cadd(cmul(p.m10,q.m00), cmul(p.m11,q.m10));
    r.m11 = cadd(cmul(p.m10,q.m01), cmul(p.m11,q.m11));
    return r;
}

template<int M>
__device__ __forceinline__ void g1q(float* Sr, float* Si, M2 g) {
    #pragma unroll
    for (int i = 0; i < 32; ++i) {
        if ((i & M) == 0) {
            const int j = i | M;
            float ar = Sr[i], ai = Si[i], br = Sr[j], bi = Si[j];
            Sr[i] = g.m00.re*ar - g.m00.im*ai + g.m01.re*br - g.m01.im*bi;
            Si[i] = g.m00.re*ai + g.m00.im*ar + g.m01.re*bi + g.m01.im*br;
            Sr[j] = g.m10.re*ar - g.m10.im*ai + g.m11.re*br - g.m11.im*bi;
            Si[j] = g.m10.re*ai + g.m10.im*ar + g.m11.re*bi + g.m11.im*br;
        }
    }
}
template<int MC, int MT>
__device__ __forceinline__ void gcrx(float* Sr, float* Si, float c, float s) {
    #pragma unroll
    for (int i = 0; i < 32; ++i) {
        if ((i & MC) != 0 && (i & MT) == 0) {
            const int j = i | MT;
            float a0r = Sr[i], a0i = Si[i], a1r = Sr[j], a1i = Si[j];
            Sr[i] = c*a0r + s*a1i;
            Si[i] = c*a0i - s*a1r;
            Sr[j] = s*a0i + c*a1r;
            Si[j] = c*a1i - s*a0r;
        }
    }
}

__device__ __forceinline__ unsigned long long pack2(float lo, float hi) {
    unsigned long long r;
    asm("mov.b64 %0, {%1, %2};" : "=l"(r) : "r"(__float_as_uint(lo)), "r"(__float_as_uint(hi)));
    return r;
}
__device__ __forceinline__ void unpack2(unsigned long long v, float& lo, float& hi) {
    unsigned a, b;
    asm("mov.b64 {%0, %1}, %2;" : "=r"(a), "=r"(b) : "l"(v));
    lo = __uint_as_float(a); hi = __uint_as_float(b);
}
__device__ __forceinline__ void fma2(unsigned long long& acc, unsigned long long a, unsigned long long b) {
    asm("fma.rn.f32x2 %0, %1, %2, %0;" : "+l"(acc) : "l"(a), "l"(b));
}

__global__ __launch_bounds__(128)
void qrnn_kernel(const float* __restrict__ x,
                 const float* __restrict__ hidden,
                 const float* __restrict__ params,
                 float* __restrict__ out)
{
    const int b = blockIdx.x;
    __shared__ float Tre[32][33];
    __shared__ float Tim[32][33];

    if (threadIdx.x < 32) {
        // ================= warp 0: hidden recurrence (5-qubit sim) =================
        const int lane = threadIdx.x;

        // z_q lives on lane 1<<(4-q).  Map special lanes -> qubit index.
        const bool special = (__popc(lane) == 1) && (lane <= 16);
        const int q_of_lane = special ? (__clz(lane) - 27) : 0;   // lane 16->q0 ... lane 1->q4

        // layer-0 hidden gate for this lane's qubit
        M2 h1 = fuse_zyx(params[3*q_of_lane], params[3*q_of_lane+1], params[3*q_of_lane+2]);

        // ---- precompute fixed 32x32 unitary U = CRX1 * G2 * CRX0 (column per lane) ----
        unsigned long long PRr[16], PRi[16], PnRi[16];
        {
            M2 h2[5];
            #pragma unroll
            for (int q = 0; q < 5; q++)
                h2[q] = fuse_zyx(params[37+3*q], params[37+3*q+1], params[37+3*q+2]);
            float cx[8], sx[8];
            #pragma unroll
            for (int k = 0; k < 8; k++) {
                int l = k >> 2, kk = k & 3;
                sincosf(0.5f*params[l*37 + 15 + kk], &sx[k], &cx[k]);
            }

            float Sr[32], Si[32];
            #pragma unroll
            for (int i = 0; i < 32; ++i) { Sr[i] = (i == lane) ? 1.f : 0.f; Si[i] = 0.f; }

            gcrx<16,8>(Sr, Si, cx[0], sx[0]);
            gcrx< 8,4>(Sr, Si, cx[1], sx[1]);
            gcrx< 4,2>(Sr, Si, cx[2], sx[2]);
            gcrx< 2,1>(Sr, Si, cx[3], sx[3]);
            g1q<16>(Sr, Si, h2[0]);
            g1q< 8>(Sr, Si, h2[1]);
            g1q< 4>(Sr, Si, h2[2]);
            g1q< 2>(Sr, Si, h2[3]);
            g1q< 1>(Sr, Si, h2[4]);
            gcrx<16,8>(Sr, Si, cx[4], sx[4]);
            gcrx< 8,4>(Sr, Si, cx[5], sx[5]);
            gcrx< 4,2>(Sr, Si, cx[6], sx[6]);
            gcrx< 2,1>(Sr, Si, cx[7], sx[7]);

            // transpose via padded SMEM: lane i ends with ROW i, packed in column pairs
            #pragma unroll
            for (int i = 0; i < 32; ++i) { Tre[i][lane] = Sr[i]; Tim[i][lane] = Si[i]; }
            __syncwarp();
            #pragma unroll
            for (int j2 = 0; j2 < 16; ++j2) {
                float r0 = Tre[lane][2*j2], r1 = Tre[lane][2*j2+1];
                float i0 = Tim[lane][2*j2], i1 = Tim[lane][2*j2+1];
                PRr[j2]  = pack2(r0, r1);
                PRi[j2]  = pack2(i0, i1);
                PnRi[j2] = pack2(-i0, -i1);
            }
        }

        float z = special ? hidden[b*NH + q_of_lane] : 0.f;

        #pragma unroll 1
        for (int t = 0; t < SEQ; ++t) {
            // ---- per-qubit 2-vector w = h1 * (cos, -i sin)  (on special lanes) ----
            float cc, ss;
            __sincosf(0.5f*z, &ss, &cc);
            float w0r = h1.m00.re*cc + h1.m01.im*ss;
            float w0i = h1.m00.im*cc - h1.m01.re*ss;
            float w1r = h1.m10.re*cc + h1.m11.im*ss;
            float w1i = h1.m10.im*cc - h1.m11.re*ss;

            // ---- embed: broadcast w from lane 1<<(4-q), depth-3 product tree ----
            float vr[5], vi[5];
            #pragma unroll
            for (int q = 0; q < 5; q++) {
                const int src = 1 << (4 - q);
                float a0r = __shfl_sync(0xffffffffu, w0r, src);
                float a0i = __shfl_sync(0xffffffffu, w0i, src);
                float b1r = __shfl_sync(0xffffffffu, w1r, src);
                float b1i = __shfl_sync(0xffffffffu, w1i, src);
                int bit = (lane >> (4 - q)) & 1;
                vr[q] = bit ? b1r : a0r;
                vi[q] = bit ? b1i : a0i;
            }
            float p01r = vr[0]*vr[1] - vi[0]*vi[1], p01i = vr[0]*vi[1] + vi[0]*vr[1];
            float p23r = vr[2]*vr[3] - vi[2]*vi[3], p23i = vr[2]*vi[3] + vi[2]*vr[3];
            float p03r = p01r*p23r - p01i*p23i,     p03i = p01r*p23i + p01i*p23r;
            float ar   = p03r*vr[4] - p03i*vi[4],   ai   = p03r*vi[4] + p03i*vr[4];

            // ---- dense matvec amp' = U*amp with packed f32x2 FMAs ----
            unsigned long long accRA = 0ull, accRB = 0ull, accIA = 0ull, accIB = 0ull;
            #pragma unroll
            for (int j2 = 0; j2 < 16; ++j2) {
                const int j = 2*j2;
                float b0r = __shfl_sync(0xffffffffu, ar, j);
                float b0i = __shfl_sync(0xffffffffu, ai, j);
                float b1r = __shfl_sync(0xffffffffu, ar, j+1);
                float b1i = __shfl_sync(0xffffffffu, ai, j+1);
                unsigned long long brr = pack2(b0r, b1r);
                unsigned long long bii = pack2(b0i, b1i);
                fma2(accRA, PRr[j2],  brr);   // + Rr*br
                fma2(accRB, PnRi[j2], bii);   // - Ri*bi
                fma2(accIA, PRr[j2],  bii);   // + Rr*bi
                fma2(accIB, PRi[j2],  brr);   // + Ri*br
            }
            float x0, x1, y0, y1, u0, u1, v0, v1;
            unpack2(accRA, x0, x1); unpack2(accRB, y0, y1);
            unpack2(accIA, u0, u1); unpack2(accIB, v0, v1);
            float nar = (x0 + x1) + (y0 + y1);
            float nai = (u0 + u1) + (v0 + v1);

            // ---- measure: Walsh-Hadamard signed butterfly; lane 1<<(4-q) keeps z_q ----
            float v = fmaf(nar, nar, nai*nai);
            #pragma unroll
            for (int m = 16; m >= 1; m >>= 1) {
                float o = __shfl_xor_sync(0xffffffffu, v, m);
                v = (lane & m) ? (o - v) : (v + o);
            }
            z = special ? v : 0.f;
        }
        if (special) out[BATCH*SEQ*NV + b*NH + q_of_lane] = z;

    } else {
        // ============ warps 1-3: closed-form outputs for this batch ============
        const int t = threadIdx.x - 32;
        if (t >= SEQ) return;

        float Cc[6], Dd[6], Ee[6];
        #pragma unroll
        for (int q = 0; q < 6; q++) {
            M2 u0 = fuse_zyx(params[19+3*q],    params[20+3*q],    params[21+3*q]);
            M2 u1 = fuse_zyx(params[37+19+3*q], params[37+20+3*q], params[37+21+3*q]);
            M2 M = mmul(u1, u0);
            float h00 = (M.m00.re*M.m00.re + M.m00.im*M.m00.im)
                      - (M.m10.re*M.m10.re + M.m10.im*M.m10.im);
            float h11 = (M.m01.re*M.m01.re + M.m01.im*M.m01.im)
                      - (M.m11.re*M.m11.re + M.m11.im*M.m11.im);
            float imh01 = (M.m00.re*M.m01.im - M.m00.im*M.m01.re)
                        - (M.m10.re*M.m11.im - M.m10.im*M.m11.re);
            Cc[q] = 0.5f*(h00 + h11);
            Dd[q] = 0.5f*(h00 - h11);
            Ee[q] = imh01;
        }

        const int P = b * SEQ + t;
        const float4* x4 = (const float4*)(x + (size_t)P * FEAT);
        float vals[60];
        #pragma unroll
        for (int i = 0; i < 15; i++) {
            float4 v4 = x4[i];
            vals[4*i+0] = v4.x; vals[4*i+1] = v4.y;
            vals[4*i+2] = v4.z; vals[4*i+3] = v4.w;
        }
        float pooled[6];
        #pragma unroll
        for (int v = 0; v < 6; v++) {
            float s = 0.f;
            #pragma unroll
            for (int j = 0; j < 10; j++) s += vals[v*10 + j];
            pooled[v] = 0.1f * s;
        }
        float mn = pooled[0], mx = pooled[0];
        #pragma unroll
        for (int v = 1; v < 6; v++) {
            mn = fminf(mn, pooled[v]);
            mx = fmaxf(mx, pooled[v]);
        }
        float scale = TWO_PI / (mx - mn + 1e-8f);
        #pragma unroll
        for (int v = 0; v < 6; v++) {
            float a = scale * (pooled[v] - mn);
            float sa, ca;
            sincosf(a, &sa, &ca);
            out[(size_t)P*6 + v] = Cc[v] + Dd[v]*ca + Ee[v]*sa;
        }
    }
}

extern "C" void kernel_launch(void* const* d_in, const int* in_sizes, int n_in,
                              void* d_out, int out_size) {
    const float* x      = (const float*)d_in[0];
    const float* hidden = (const float*)d_in[1];
    const float* params = (const float*)d_in[2];
    float* out = (float*)d_out;
    qrnn_kernel<<<BATCH, 128>>>(x, hidden, params, out);
}